// round 1
// baseline (speedup 1.0000x reference)
#include <cuda_runtime.h>
#include <math.h>

// Grid: (2, 40, 40, 40). Per batch 64000 voxels.
#define NVOX   64000
#define HW     1600      // 40*40
#define WW     40
#define NWORDS 1000      // 64000 / 64 bits
#define BPB    8         // blocks per batch
#define NB     16        // total blocks (2 batches * BPB)
#define TPB    1024
#define SLICE  (NVOX / BPB)   // 8000 voxels per block

__device__ float g_psum[NB];
__device__ int   g_pcnt[NB];

__global__ __launch_bounds__(TPB, 1)
void mdist_main(const float* __restrict__ inp, const float* __restrict__ tgt) {
    __shared__ unsigned long long smask[NWORDS];
    __shared__ float ssum[TPB];
    __shared__ int   scnt[TPB];

    const int tid   = threadIdx.x;
    const int b     = blockIdx.x;
    const int batch = b / BPB;
    const int slice = b % BPB;
    const int warp  = tid >> 5;
    const int lane  = tid & 31;

    const float* t = tgt + batch * NVOX;
    const float* p = inp + batch * NVOX;

    // ---- Build occupancy bitmask of true voxels (target > 0) in shared ----
    // Warp w handles words w, w+32, w+64, ... Each word = 64 consecutive voxels,
    // assembled from two ballots (fully coalesced 128B reads, no atomics).
    for (int w = warp; w < NWORDS; w += 32) {
        const int base = w << 6;
        unsigned m0 = __ballot_sync(0xffffffffu, t[base + lane]      > 0.0f);
        unsigned m1 = __ballot_sync(0xffffffffu, t[base + 32 + lane] > 0.0f);
        if (lane == 0)
            smask[w] = (unsigned long long)m0 | ((unsigned long long)m1 << 32);
    }
    __syncthreads();

    // ---- Scan this block's slice of input for pred voxels, shell-search ----
    float lsum = 0.0f;
    int   lcnt = 0;
    const int vbase = slice * SLICE;

    for (int j = tid; j < SLICE; j += TPB) {
        const int v = vbase + j;
        const float val = p[v];
        if (val > 2.0f) {
            lcnt++;
            const int z   = v / HW;
            const int rem = v - z * HW;
            const int y   = rem / WW;
            const int x   = rem - y * WW;

            int best = 0x7fffffff;   // min d^2 found so far
            // Expanding Chebyshev cubes. Any unscanned voxel after radius r has
            // d^2 >= (r+1)^2, so best <= (r+1)^2 is a safe stop. With density
            // ~0.5 this terminates at r<=1 with probability 1 - 7e-9.
            for (int r = 0;; ++r) {
                const int z0 = max(z - r, 0), z1 = min(z + r, 39);
                const int y0 = max(y - r, 0), y1 = min(y + r, 39);
                const int x0 = max(x - r, 0), x1 = min(x + r, 39);
                for (int zz = z0; zz <= z1; ++zz) {
                    const int dz  = zz - z;
                    const int dz2 = dz * dz;
                    for (int yy = y0; yy <= y1; ++yy) {
                        const int dy   = yy - y;
                        const int dzy  = dz2 + dy * dy;
                        const int rowb = zz * HW + yy * WW;
                        for (int xx = x0; xx <= x1; ++xx) {
                            const int idx = rowb + xx;
                            if ((smask[idx >> 6] >> (idx & 63)) & 1ULL) {
                                const int dx = xx - x;
                                const int d2 = dzy + dx * dx;
                                best = min(best, d2);
                            }
                        }
                    }
                }
                if (best <= (r + 1) * (r + 1) || r >= 39) break;
            }
            // If no true voxel exists anywhere, reference defines distance = 0.
            if (best != 0x7fffffff) lsum += sqrtf((float)best);
        }
    }

    // ---- Deterministic fixed-order block reduction ----
    ssum[tid] = lsum;
    scnt[tid] = lcnt;
    __syncthreads();
    for (int s = TPB / 2; s > 0; s >>= 1) {
        if (tid < s) {
            ssum[tid] += ssum[tid + s];
            scnt[tid] += scnt[tid + s];
        }
        __syncthreads();
    }
    if (tid == 0) {
        g_psum[b] = ssum[0];
        g_pcnt[b] = scnt[0];
    }
}

__global__ void mdist_finalize(float* __restrict__ out, int out_size) {
    // Single thread, fixed summation order -> bit-deterministic across replays.
    float s = 0.0f;
    int   c = 0;
#pragma unroll
    for (int i = 0; i < NB; ++i) { s += g_psum[i]; c += g_pcnt[i]; }
    const float v = (c > 0) ? (s / (float)c) : 0.0f;
    for (int i = 0; i < out_size; ++i) out[i] = v;
}

extern "C" void kernel_launch(void* const* d_in, const int* in_sizes, int n_in,
                              void* d_out, int out_size) {
    const float* inp = (const float*)d_in[0];
    const float* tgt = (const float*)d_in[1];
    float* out = (float*)d_out;
    (void)in_sizes; (void)n_in;

    mdist_main<<<NB, TPB>>>(inp, tgt);
    mdist_finalize<<<1, 1>>>(out, out_size);
}

// round 2
// speedup vs baseline: 1.1213x; 1.1213x over previous
#include <cuda_runtime.h>
#include <math.h>

// Grid: (2, 40, 40, 40). Per batch 64000 voxels.
#define NVOX   64000
#define HW     1600      // 40*40
#define WW     40
#define NW64   1000      // 64000 / 64 bits
#define BPB    8         // blocks per batch
#define NB     16        // total blocks (2 batches * BPB)
#define TPB    1024
#define SLICE  (NVOX / BPB)   // 8000 voxels per block

__device__ float    g_psum[NB];
__device__ int      g_pcnt[NB];
__device__ unsigned g_arrive = 0;   // reset by last block each run (graph-replay safe)

__global__ __launch_bounds__(TPB, 1)
void mdist_fused(const float* __restrict__ inp, const float* __restrict__ tgt,
                 float* __restrict__ out, int out_size) {
    __shared__ unsigned long long smask[NW64];
    __shared__ float wsum[32];
    __shared__ int   wcnt[32];

    const int tid   = threadIdx.x;
    const int b     = blockIdx.x;
    const int batch = b >> 3;          // b / BPB
    const int slice = b & 7;           // b % BPB
    const int warp  = tid >> 5;
    const int lane  = tid & 31;

    const float* t = tgt + batch * NVOX;
    const float* p = inp + batch * NVOX;
    const int vbase = slice * SLICE;

    // ---- Prefetch this thread's pred-slice values (overlaps mask build) ----
    float pv[8];
#pragma unroll
    for (int k = 0; k < 8; ++k) {
        const int j = tid + k * TPB;
        pv[k] = (j < SLICE) ? p[vbase + j] : 0.0f;
    }

    // ---- Build occupancy bitmask of true voxels (target > 0) in shared ----
    // Warp w handles words w, w+32, ... Chunked prefetch (16 independent loads)
    // before the ballots breaks the load->ballot serial chain (MLP 1 -> 16).
#pragma unroll
    for (int c = 0; c < 4; ++c) {
        float a[8], bb[8];
        int   wv[8];
#pragma unroll
        for (int k = 0; k < 8; ++k) {
            const int w = warp + (c * 8 + k) * 32;
            wv[k] = w;
            if (w < NW64) {
                a[k]  = t[(w << 6) + lane];
                bb[k] = t[(w << 6) + 32 + lane];
            }
        }
#pragma unroll
        for (int k = 0; k < 8; ++k) {
            if (wv[k] < NW64) {   // warp-uniform branch
                unsigned m0 = __ballot_sync(0xffffffffu, a[k]  > 0.0f);
                unsigned m1 = __ballot_sync(0xffffffffu, bb[k] > 0.0f);
                if (lane == 0)
                    smask[wv[k]] = (unsigned long long)m0 |
                                   ((unsigned long long)m1 << 32);
            }
        }
    }
    __syncthreads();

    // ---- Shell search for each pred voxel (input > 2.0) ----
    float lsum = 0.0f;
    int   lcnt = 0;
#pragma unroll
    for (int k = 0; k < 8; ++k) {
        if (pv[k] > 2.0f) {
            lcnt++;
            const int v   = vbase + tid + k * TPB;
            const int z   = v / HW;
            const int rem = v - z * HW;
            const int y   = rem / WW;
            const int x   = rem - y * WW;

            int best = 0x7fffffff;
            // Expanding Chebyshev cubes: after radius r every unscanned voxel
            // has d^2 >= (r+1)^2, so best <= (r+1)^2 is a safe stop. Density
            // ~0.5 -> terminates at r<=1 with prob 1-7e-9.
            for (int r = 0;; ++r) {
                const int z0 = max(z - r, 0), z1 = min(z + r, 39);
                const int y0 = max(y - r, 0), y1 = min(y + r, 39);
                const int x0 = max(x - r, 0), x1 = min(x + r, 39);
                for (int zz = z0; zz <= z1; ++zz) {
                    const int dz  = zz - z;
                    const int dz2 = dz * dz;
                    for (int yy = y0; yy <= y1; ++yy) {
                        const int dy   = yy - y;
                        const int dzy  = dz2 + dy * dy;
                        const int rowb = zz * HW + yy * WW;
                        for (int xx = x0; xx <= x1; ++xx) {
                            const int idx = rowb + xx;
                            if ((smask[idx >> 6] >> (idx & 63)) & 1ULL) {
                                const int dx = xx - x;
                                best = min(best, dzy + dx * dx);
                            }
                        }
                    }
                }
                if (best <= (r + 1) * (r + 1) || r >= 39) break;
            }
            if (best != 0x7fffffff) lsum += sqrtf((float)best);
        }
    }

    // ---- Deterministic reduction: warp shuffles, then warp 0 ----
#pragma unroll
    for (int off = 16; off; off >>= 1) {
        lsum += __shfl_down_sync(0xffffffffu, lsum, off);
        lcnt += __shfl_down_sync(0xffffffffu, lcnt, off);
    }
    if (lane == 0) { wsum[warp] = lsum; wcnt[warp] = lcnt; }
    __syncthreads();

    if (warp == 0) {
        float s = wsum[lane];
        int   c = wcnt[lane];
#pragma unroll
        for (int off = 16; off; off >>= 1) {
            s += __shfl_down_sync(0xffffffffu, s, off);
            c += __shfl_down_sync(0xffffffffu, c, off);
        }
        if (lane == 0) {
            g_psum[b] = s;
            g_pcnt[b] = c;
            __threadfence();
            const unsigned prev = atomicAdd(&g_arrive, 1u);
            if (prev == NB - 1) {
                // Last block: fixed-order combine -> bit-deterministic.
                float ts = 0.0f; int tc = 0;
#pragma unroll
                for (int i = 0; i < NB; ++i) { ts += g_psum[i]; tc += g_pcnt[i]; }
                const float val = (tc > 0) ? (ts / (float)tc) : 0.0f;
                for (int i = 0; i < out_size; ++i) out[i] = val;
                g_arrive = 0;   // reset for next graph replay
            }
        }
    }
}

extern "C" void kernel_launch(void* const* d_in, const int* in_sizes, int n_in,
                              void* d_out, int out_size) {
    const float* inp = (const float*)d_in[0];
    const float* tgt = (const float*)d_in[1];
    (void)in_sizes; (void)n_in;
    mdist_fused<<<NB, TPB>>>(inp, tgt, (float*)d_out, out_size);
}

// round 3
// speedup vs baseline: 1.5152x; 1.3514x over previous
#include <cuda_runtime.h>
#include <math.h>

// Grid: (2, 40, 40, 40). 128000 voxels total, 3200 (z,y)-rows of 40 voxels.
#define NVOX    64000
#define NROWS   3200          // 2 batches * 40*40 rows
#define GRID    148
#define TPB     256
#define NWARPS  (GRID * (TPB / 32))   // 1184
#define NF4     32000         // 128000 / 4

__device__ unsigned long long g_rows[NROWS];  // row (b,z,y) -> 40-bit occupancy
__device__ float    g_psum[GRID];
__device__ int      g_pcnt[GRID];
__device__ unsigned g_arr1 = 0, g_rel1 = 0, g_arr2 = 0;

// min over set bits of (bitpos - x)^2 ; large sentinel if row empty
__device__ __forceinline__ int row_d2(unsigned long long w, int x) {
    if (w == 0ULL) return 1 << 20;
    unsigned long long low  = w & ((1ULL << (x + 1)) - 1ULL); // bits 0..x
    unsigned long long high = (w >> x) >> 1;                  // bits x+1..
    int dl = low  ? (x - (63 - __clzll(low))) : (1 << 10);
    int dh = high ? __ffsll((long long)high)  : (1 << 10);
    int d  = min(dl, dh);
    return d * d;
}

__global__ __launch_bounds__(TPB, 8)
void mdist_onepass(const float* __restrict__ inp, const float* __restrict__ tgt,
                   float* __restrict__ out, int out_size) {
    __shared__ float wsum[8];
    __shared__ int   wcnt[8];

    const int tid  = threadIdx.x;
    const int bid  = blockIdx.x;
    const int lane = tid & 31;
    const int warp = tid >> 5;
    const int gw   = bid * (TPB / 32) + warp;   // global warp id

    // ================= Phase A: build row bitmask in global ===============
    // Row R (0..3199) = consecutive 40 floats of tgt starting at R*40.
    {
        float va[3], vb[3]; int Rs[3]; int n = 0;
#pragma unroll
        for (int i = 0; i < 3; ++i) {
            const int R = gw + i * NWARPS;
            if (R < NROWS) {
                Rs[n] = R;
                va[n] = tgt[R * 40 + lane];
                vb[n] = (lane < 8) ? tgt[R * 40 + 32 + lane] : -1.0f;
                n++;
            }
        }
        for (int i = 0; i < n; ++i) {
            unsigned m0 = __ballot_sync(0xffffffffu, va[i] > 0.0f);
            unsigned m1 = __ballot_sync(0xffffffffu, vb[i] > 0.0f) & 0xffu;
            if (lane == 0)
                g_rows[Rs[i]] = (unsigned long long)m0 |
                                ((unsigned long long)m1 << 32);
        }
    }

    // ================= Grid barrier (all 148 blocks co-resident) ==========
    __syncthreads();
    if (tid == 0) {
        __threadfence();
        unsigned p = atomicAdd(&g_arr1, 1u);
        if (p == GRID - 1) atomicExch(&g_rel1, 1u);
        else while (*(volatile unsigned*)&g_rel1 == 0u) {}
        __threadfence();
    }
    __syncthreads();

    // ================= Phase B: scan preds, row-wise 1-NN =================
    float lsum = 0.0f;
    int   lcnt = 0;
    const int g = bid * TPB + tid;          // one float4 per thread, g < 32000
    if (g < NF4) {
        const float4 q = ((const float4*)inp)[g];
        const float qa[4] = {q.x, q.y, q.z, q.w};
#pragma unroll
        for (int c = 0; c < 4; ++c) {
            if (qa[c] > 2.0f) {
                lcnt++;
                const int v     = 4 * g + c;
                const int batch = v / NVOX;
                const int loc   = v - batch * NVOX;
                const int z     = loc / 1600;
                const int rem   = loc - z * 1600;
                const int y     = rem / 40;
                const int x     = rem - y * 40;
                const unsigned long long* rows = g_rows + batch * 1600;

                // 9 independent row loads (dz,dy in [-1,1]) -> one L2 trip
                unsigned long long w9[9];
#pragma unroll
                for (int dz = -1; dz <= 1; ++dz)
#pragma unroll
                    for (int dy = -1; dy <= 1; ++dy) {
                        const int zz = z + dz, yy = y + dy;
                        const bool ok = (unsigned)zz < 40u && (unsigned)yy < 40u;
                        w9[(dz + 1) * 3 + (dy + 1)] =
                            ok ? rows[zz * 40 + yy] : 0ULL;
                    }

                int best = 1 << 24;
#pragma unroll
                for (int dz = -1; dz <= 1; ++dz)
#pragma unroll
                    for (int dy = -1; dy <= 1; ++dy) {
                        const int dzy = dz * dz + dy * dy;
                        const int d2  = dzy + row_d2(w9[(dz + 1) * 3 + (dy + 1)], x);
                        best = min(best, d2);
                    }

                // Rare fallback: expanding Chebyshev rings of whole rows.
                // After ring r, every unscanned row has dz^2+dy^2 >= (r+1)^2.
                if (best > 4) {
                    for (int r = 2; r <= 39; ++r) {
                        if (best <= r * r) break;
                        for (int dz = -r; dz <= r; ++dz) {
                            const int zz = z + dz;
                            if ((unsigned)zz >= 40u) continue;
                            const int step = (abs(dz) == r) ? 1 : 2 * r;
                            for (int dy = -r; dy <= r; dy += step) {
                                const int yy = y + dy;
                                if ((unsigned)yy >= 40u) continue;
                                const int d2 = dz * dz + dy * dy +
                                               row_d2(rows[zz * 40 + yy], x);
                                best = min(best, d2);
                            }
                        }
                    }
                }
                if (best <= 4563) lsum += sqrtf((float)best); // else: no true voxels
            }
        }
    }

    // ================= Deterministic reduction + finalize =================
#pragma unroll
    for (int off = 16; off; off >>= 1) {
        lsum += __shfl_down_sync(0xffffffffu, lsum, off);
        lcnt += __shfl_down_sync(0xffffffffu, lcnt, off);
    }
    if (lane == 0) { wsum[warp] = lsum; wcnt[warp] = lcnt; }
    __syncthreads();

    if (tid == 0) {
        float s = 0.0f; int c = 0;
#pragma unroll
        for (int i = 0; i < 8; ++i) { s += wsum[i]; c += wcnt[i]; }
        g_psum[bid] = s;
        g_pcnt[bid] = c;
        __threadfence();
        const unsigned prev = atomicAdd(&g_arr2, 1u);
        if (prev == GRID - 1) {
            __threadfence();
            float ts = 0.0f; int tc = 0;
            for (int i = 0; i < GRID; ++i) { ts += g_psum[i]; tc += g_pcnt[i]; }
            const float val = (tc > 0) ? (ts / (float)tc) : 0.0f;
            for (int i = 0; i < out_size; ++i) out[i] = val;
            g_arr1 = 0; g_rel1 = 0; g_arr2 = 0;   // reset for graph replay
        }
    }
}

extern "C" void kernel_launch(void* const* d_in, const int* in_sizes, int n_in,
                              void* d_out, int out_size) {
    const float* inp = (const float*)d_in[0];
    const float* tgt = (const float*)d_in[1];
    (void)in_sizes; (void)n_in;
    mdist_onepass<<<GRID, TPB>>>(inp, tgt, (float*)d_out, out_size);
}

// round 4
// speedup vs baseline: 1.6766x; 1.1065x over previous
#include <cuda_runtime.h>
#include <math.h>

// Input: (2, 40, 40, 40) fp32. 64000 voxels/batch, rows of 40 along x.
#define NVOX   64000
#define GRID   32          // 16 blocks per batch
#define TPB    1024
#define BPBAT  16
#define VPB    4000        // voxels per block (2.5 z-planes)
#define F4PB   1000        // float4 per block

__device__ float    g_psum[GRID];
__device__ int      g_pcnt[GRID];
__device__ unsigned g_arr = 0;   // reset by last block (graph-replay safe)

// min over set bits of (bitpos - x)^2 ; large sentinel if row empty
__device__ __forceinline__ int row_d2(unsigned long long w, int x) {
    if (w == 0ULL) return 1 << 20;
    unsigned long long low  = w & ((1ULL << (x + 1)) - 1ULL);
    unsigned long long high = (w >> x) >> 1;
    int dl = low  ? (x - (63 - __clzll(low))) : (1 << 10);
    int dh = high ? __ffsll((long long)high)  : (1 << 10);
    int d  = min(dl, dh);
    return d * d;
}

// Fallback only (probability ~2^-45 per pred): scan a target row from global.
__device__ __noinline__ int global_row_d2(const float* __restrict__ t,
                                          int zz, int yy, int x) {
    const float* r = t + zz * 1600 + yy * 40;
    int best = 1 << 20;
    for (int xx = 0; xx < 40; ++xx)
        if (r[xx] > 0.0f) { int dx = xx - x; best = min(best, dx * dx); }
    return best;
}

__global__ __launch_bounds__(TPB, 1)
void mdist_slab(const float* __restrict__ inp, const float* __restrict__ tgt,
                float* __restrict__ out, int out_size) {
    __shared__ unsigned long long srow[256];   // slab+halo rows, <=200 used
    __shared__ float wsum[32];
    __shared__ int   wcnt[32];

    const int tid   = threadIdx.x;
    const int bid   = blockIdx.x;
    const int lane  = tid & 31;
    const int warp  = tid >> 5;
    const int batch = bid >> 4;        // bid / BPBAT
    const int slice = bid & 15;        // bid % BPBAT

    const float* t = tgt + batch * NVOX;

    // ---- Prefetch this thread's float4 of input (overlaps mask build) ----
    float4 q = make_float4(0.f, 0.f, 0.f, 0.f);
    if (tid < F4PB) q = ((const float4*)inp)[batch * (NVOX / 4) + slice * F4PB + tid];

    // ---- Slab z-range with +-1 halo ----
    const int zlo_p = (slice * VPB) / 1600;
    const int zhi_p = (slice * VPB + VPB - 1) / 1600;
    const int zlo   = max(zlo_p - 1, 0);
    const int zhi   = min(zhi_p + 1, 39);
    const int nrows = (zhi - zlo + 1) * 40;    // <= 200

    // ---- Build slab row-mask in shared (prefetch then ballot) ----
    {
        float va[7], vb[7];
#pragma unroll
        for (int i = 0; i < 7; ++i) {
            const int r = warp + i * 32;
            if (r < nrows) {
                const int off = (zlo * 40 + r) * 40;
                va[i] = t[off + lane];
                vb[i] = (lane < 8) ? t[off + 32 + lane] : -1.0f;
            }
        }
#pragma unroll
        for (int i = 0; i < 7; ++i) {
            const int r = warp + i * 32;
            if (r < nrows) {   // warp-uniform
                unsigned m0 = __ballot_sync(0xffffffffu, va[i] > 0.0f);
                unsigned m1 = __ballot_sync(0xffffffffu, vb[i] > 0.0f) & 0xffu;
                if (lane == 0)
                    srow[r] = (unsigned long long)m0 |
                              ((unsigned long long)m1 << 32);
            }
        }
    }
    __syncthreads();

    // ---- Pred scan: row-wise 1-NN from shared mask ----
    float lsum = 0.0f;
    int   lcnt = 0;
    if (tid < F4PB) {
        const float qa[4] = {q.x, q.y, q.z, q.w};
#pragma unroll
        for (int c = 0; c < 4; ++c) {
            if (qa[c] > 2.0f) {
                lcnt++;
                const int loc = slice * VPB + tid * 4 + c;
                const int z   = loc / 1600;
                const int rem = loc - z * 1600;
                const int y   = rem / 40;
                const int x   = rem - y * 40;

                int best = 1 << 24;
#pragma unroll
                for (int dz = -1; dz <= 1; ++dz)
#pragma unroll
                    for (int dy = -1; dy <= 1; ++dy) {
                        const int zz = z + dz, yy = y + dy;
                        unsigned long long w = 0ULL;
                        if ((unsigned)zz < 40u && (unsigned)yy < 40u)
                            w = srow[(zz - zlo) * 40 + yy];
                        best = min(best, dz * dz + dy * dy + row_d2(w, x));
                    }

                // Rare fallback: expanding rings of whole rows from global.
                // After ring r every unscanned row has dz^2+dy^2 >= (r+1)^2.
                if (best > 4) {
                    for (int r = 2; r <= 39; ++r) {
                        if (best <= r * r) break;
                        for (int dz = -r; dz <= r; ++dz) {
                            const int zz = z + dz;
                            if ((unsigned)zz >= 40u) continue;
                            const int step = (abs(dz) == r) ? 1 : 2 * r;
                            for (int dy = -r; dy <= r; dy += step) {
                                const int yy = y + dy;
                                if ((unsigned)yy >= 40u) continue;
                                best = min(best, dz * dz + dy * dy +
                                                 global_row_d2(t, zz, yy, x));
                            }
                        }
                    }
                }
                if (best <= 4563) lsum += sqrtf((float)best); // else: no true voxels
            }
        }
    }

    // ---- Deterministic reduction ----
#pragma unroll
    for (int off = 16; off; off >>= 1) {
        lsum += __shfl_down_sync(0xffffffffu, lsum, off);
        lcnt += __shfl_down_sync(0xffffffffu, lcnt, off);
    }
    if (lane == 0) { wsum[warp] = lsum; wcnt[warp] = lcnt; }
    __syncthreads();

    if (warp == 0) {
        float s = wsum[lane];
        int   c = wcnt[lane];
#pragma unroll
        for (int off = 16; off; off >>= 1) {
            s += __shfl_down_sync(0xffffffffu, s, off);
            c += __shfl_down_sync(0xffffffffu, c, off);
        }
        if (lane == 0) {
            g_psum[bid] = s;
            g_pcnt[bid] = c;
            __threadfence();
            const unsigned prev = atomicAdd(&g_arr, 1u);
            if (prev == GRID - 1) {
                __threadfence();
                float ts = 0.0f; int tc = 0;
#pragma unroll
                for (int i = 0; i < GRID; ++i) { ts += g_psum[i]; tc += g_pcnt[i]; }
                const float val = (tc > 0) ? (ts / (float)tc) : 0.0f;
                for (int i = 0; i < out_size; ++i) out[i] = val;
                g_arr = 0;   // reset for next graph replay
            }
        }
    }
}

extern "C" void kernel_launch(void* const* d_in, const int* in_sizes, int n_in,
                              void* d_out, int out_size) {
    const float* inp = (const float*)d_in[0];
    const float* tgt = (const float*)d_in[1];
    (void)in_sizes; (void)n_in;
    mdist_slab<<<GRID, TPB>>>(inp, tgt, (float*)d_out, out_size);
}

// round 5
// speedup vs baseline: 2.6617x; 1.5875x over previous
#include <cuda_runtime.h>
#include <math.h>

// Input: (2, 40, 40, 40) fp32. Rows of 40 along x; 40 % 4 == 0.
#define NVOX   64000
#define GRID   128
#define TPB    256
#define VPB    1000        // voxels per block
#define F4PB   250         // float4 per block
#define SROWN  252         // padded mask: (4+2 planes) * 42 y-slots

typedef unsigned long long u64;

__device__ u64      g_acc = 0ULL;   // [63:44] count, [43:0] sum * 2^24
__device__ unsigned g_arr = 0;      // reset by last block (graph-replay safe)

// min over set bits of (bitpos - x)^2 ; ~(1<<20) sentinel if empty
__device__ __forceinline__ int row_d2(u64 w, int x) {
    u64 low  = w & ((2ULL << x) - 1ULL);   // bits 0..x
    u64 high = (w >> x) >> 1;              // bits x+1..
    int dl = low  ? (x - (63 - __clzll((long long)low))) : (1 << 10);
    int dh = high ? __ffsll((long long)high)             : (1 << 10);
    int d  = min(dl, dh);
    return d * d;
}

// Fallback only (P ~ 2^-33 per pred): scan a target row straight from global.
__device__ __noinline__ int global_row_d2(const float* __restrict__ t,
                                          int zz, int yy, int x) {
    const float* r = t + zz * 1600 + yy * 40;
    int best = 1 << 20;
    for (int xx = 0; xx < 40; ++xx)
        if (r[xx] > 0.0f) { int dx = xx - x; best = min(best, dx * dx); }
    return best;
}

__global__ __launch_bounds__(TPB, 1)
void mdist_v5(const float* __restrict__ inp, const float* __restrict__ tgt,
              float* __restrict__ out, int out_size) {
    __shared__ u64   srow[SROWN];
    __shared__ float wsum[8];
    __shared__ int   wcnt[8];

    const int tid   = threadIdx.x;
    const int bid   = blockIdx.x;
    const int lane  = tid & 31;
    const int warp  = tid >> 5;
    const int batch = bid >> 6;        // 64 blocks per batch
    const int slice = bid & 63;

    const float* t = tgt + batch * NVOX;

    // ---- Prefetch this thread's float4 of input ----
    float4 q = make_float4(0.f, 0.f, 0.f, 0.f);
    if (tid < F4PB)
        q = ((const float4*)inp)[batch * (NVOX / 4) + slice * F4PB + tid];

    // ---- Slab z-range with +-1 halo (<= 4 planes) ----
    const int zlo_p = (slice * VPB) / 1600;
    const int zhi_p = (slice * VPB + VPB - 1) / 1600;
    const int zlo   = max(zlo_p - 1, 0);
    const int zhi   = min(zhi_p + 1, 39);
    const int nplanes = zhi - zlo + 1;

    // ---- Issue ALL target row loads up-front (one latency epoch) ----
    // warp -> (plane p, y half): rows y = ybase..ybase+19 of plane zlo+p.
    const int p     = warp >> 1;
    const int ybase = (warp & 1) * 20;
    float va[20], vb[20];
    if (p < nplanes) {
        const float* rp = t + (zlo + p) * 1600 + ybase * 40;
#pragma unroll
        for (int i = 0; i < 20; ++i) {
            va[i] = rp[i * 40 + lane];
            vb[i] = (lane < 8) ? rp[i * 40 + 32 + lane] : -1.0f;
        }
    }

    // ---- Zero padded mask, then build via ballots ----
    if (tid < SROWN) srow[tid] = 0ULL;
    __syncthreads();
    if (p < nplanes) {
#pragma unroll
        for (int i = 0; i < 20; ++i) {
            unsigned m0 = __ballot_sync(0xffffffffu, va[i] > 0.0f);
            unsigned m1 = __ballot_sync(0xffffffffu, vb[i] > 0.0f) & 0xffu;
            if (lane == 0)
                srow[(p + 1) * 42 + (ybase + i) + 1] =
                    (u64)m0 | ((u64)m1 << 32);
        }
    }
    __syncthreads();

    // ---- Pred scan: decode + 9-row gather once per thread ----
    float lsum = 0.0f;
    int   lcnt = 0;
    if (tid < F4PB) {
        const float qa[4] = {q.x, q.y, q.z, q.w};
        const bool anyp = (qa[0] > 2.0f) | (qa[1] > 2.0f) |
                          (qa[2] > 2.0f) | (qa[3] > 2.0f);
        if (anyp) {
            const int loc = slice * VPB + tid * 4;   // all 4 voxels: same row
            const int z   = loc / 1600;
            const int rem = loc - z * 1600;
            const int y   = rem / 40;
            const int x0  = rem - y * 40;

            const u64* base = srow + (z - zlo + 1) * 42 + (y + 1);
            const u64 c0 = base[0];
            const u64 r1 = base[-1]  | base[1]  | base[-42] | base[42];
            const u64 r2 = base[-43] | base[-41] | base[41] | base[43];

#pragma unroll
            for (int c = 0; c < 4; ++c) {
                if (qa[c] > 2.0f) {
                    lcnt++;
                    const int x = x0 + c;
                    int best = min(min(row_d2(c0, x),
                                       row_d2(r1, x) + 1),
                                       row_d2(r2, x) + 2);
                    // Rare fallback: expanding rings of whole rows (global).
                    // After ring r every unscanned row has dz^2+dy^2>=(r+1)^2.
                    if (best > 4) {
                        for (int r = 2; r <= 39; ++r) {
                            if (best <= r * r) break;
                            for (int dz = -r; dz <= r; ++dz) {
                                const int zz = z + dz;
                                if ((unsigned)zz >= 40u) continue;
                                const int step = (abs(dz) == r) ? 1 : 2 * r;
                                for (int dy = -r; dy <= r; dy += step) {
                                    const int yy = y + dy;
                                    if ((unsigned)yy >= 40u) continue;
                                    best = min(best, dz * dz + dy * dy +
                                                     global_row_d2(t, zz, yy, x));
                                }
                            }
                        }
                    }
                    if (best <= 4563) lsum += sqrtf((float)best);
                }
            }
        }
    }

    // ---- Deterministic in-block reduction ----
#pragma unroll
    for (int off = 16; off; off >>= 1) {
        lsum += __shfl_down_sync(0xffffffffu, lsum, off);
        lcnt += __shfl_down_sync(0xffffffffu, lcnt, off);
    }
    if (lane == 0) { wsum[warp] = lsum; wcnt[warp] = lcnt; }
    __syncthreads();

    // ---- One integer atomic per block: order-independent & exact ----
    if (tid == 0) {
        float s = 0.0f; int c = 0;
#pragma unroll
        for (int i = 0; i < 8; ++i) { s += wsum[i]; c += wcnt[i]; }
        const u64 contrib = ((u64)(unsigned)c << 44) |
                            (u64)__double2ll_rn((double)s * 16777216.0);
        atomicAdd(&g_acc, contrib);
        __threadfence();
        const unsigned prev = atomicAdd(&g_arr, 1u);
        if (prev == GRID - 1) {
            __threadfence();
            const u64 v = atomicAdd(&g_acc, 0ULL);   // ordered read
            const int cnt = (int)(v >> 44);
            const double sum = (double)(v & ((1ULL << 44) - 1ULL)) *
                               (1.0 / 16777216.0);
            const float val = (cnt > 0) ? (float)(sum / (double)cnt) : 0.0f;
            for (int i = 0; i < out_size; ++i) out[i] = val;
            g_acc = 0ULL; g_arr = 0;   // reset for next graph replay
        }
    }
}

extern "C" void kernel_launch(void* const* d_in, const int* in_sizes, int n_in,
                              void* d_out, int out_size) {
    const float* inp = (const float*)d_in[0];
    const float* tgt = (const float*)d_in[1];
    (void)in_sizes; (void)n_in;
    mdist_v5<<<GRID, TPB>>>(inp, tgt, (float*)d_out, out_size);
}

// round 6
// speedup vs baseline: 2.6776x; 1.0060x over previous
#include <cuda_runtime.h>
#include <math.h>

// Input: (2, 40, 40, 40) fp32. Rows of 40 along x; 40 % 4 == 0.
#define NVOX   64000
#define GRID   64          // 32 blocks per batch
#define TPB    512
#define VPB    2000        // voxels per block (1.25 planes)
#define F4PB   500         // float4 per block
#define SROWN  252         // padded mask: (<=4+2 planes) * 42 y-slots

typedef unsigned long long u64;

// [63:57] arrivals, [56:40] pred count, [39:0] sum * 2^20.
// One integer atomicAdd per block: order-independent, bit-deterministic.
__device__ u64 g_acc = 0ULL;   // reset by last block (graph-replay safe)

// min over set bits of (bitpos - x)^2 ; ~(1<<20) sentinel if empty
__device__ __forceinline__ int row_d2(u64 w, int x) {
    u64 low  = w & ((2ULL << x) - 1ULL);   // bits 0..x
    u64 high = (w >> x) >> 1;              // bits x+1..
    int dl = low  ? (x - (63 - __clzll((long long)low))) : (1 << 10);
    int dh = high ? __ffsll((long long)high)             : (1 << 10);
    int d  = min(dl, dh);
    return d * d;
}

// Fallback only (P ~ 2^-33 per pred): scan a target row straight from global.
__device__ __noinline__ int global_row_d2(const float* __restrict__ t,
                                          int zz, int yy, int x) {
    const float* r = t + zz * 1600 + yy * 40;
    int best = 1 << 20;
    for (int xx = 0; xx < 40; ++xx)
        if (r[xx] > 0.0f) { int dx = xx - x; best = min(best, dx * dx); }
    return best;
}

__global__ __launch_bounds__(TPB, 1)
void mdist_v6(const float* __restrict__ inp, const float* __restrict__ tgt,
              float* __restrict__ out, int out_size) {
    __shared__ u64 srow[SROWN];
    __shared__ u64 wacc[16];

    const int tid   = threadIdx.x;
    const int bid   = blockIdx.x;
    const int lane  = tid & 31;
    const int warp  = tid >> 5;
    const int batch = bid >> 5;        // 32 blocks per batch
    const int slice = bid & 31;

    const float* t = tgt + batch * NVOX;

    // ---- Prefetch this thread's float4 of input ----
    float4 q = make_float4(0.f, 0.f, 0.f, 0.f);
    if (tid < F4PB)
        q = ((const float4*)inp)[batch * (NVOX / 4) + slice * F4PB + tid];

    // ---- Zero padded mask early (independent of loads; covered by sync) ----
    if (tid < SROWN) srow[tid] = 0ULL;

    // ---- Slab z-range with +-1 halo (<= 4 planes, <= 160 rows) ----
    const int zlo_p = (slice * VPB) / 1600;
    const int zhi_p = (slice * VPB + VPB - 1) / 1600;
    const int zlo   = max(zlo_p - 1, 0);
    const int zhi   = min(zhi_p + 1, 39);
    const int nrows = (zhi - zlo + 1) * 40;

    // ---- Issue ALL target row loads up-front (one latency epoch) ----
    // warp handles rows r = warp, warp+16, ... (<=10 per warp).
    float va[10], vb[10];
#pragma unroll
    for (int i = 0; i < 10; ++i) {
        const int r = warp + i * 16;
        if (r < nrows) {
            const int off = (zlo * 40 + r) * 40;
            va[i] = t[off + lane];
            vb[i] = (lane < 8) ? t[off + 32 + lane] : -1.0f;
        }
    }
    __syncthreads();   // srow zeroing complete

    // ---- Ballot rows into padded shared mask ----
#pragma unroll
    for (int i = 0; i < 10; ++i) {
        const int r = warp + i * 16;
        if (r < nrows) {   // warp-uniform
            unsigned m0 = __ballot_sync(0xffffffffu, va[i] > 0.0f);
            unsigned m1 = __ballot_sync(0xffffffffu, vb[i] > 0.0f) & 0xffu;
            if (lane == 0) {
                const int pl = r / 40, yy = r - pl * 40;
                srow[(pl + 1) * 42 + yy + 1] = (u64)m0 | ((u64)m1 << 32);
            }
        }
    }
    __syncthreads();

    // ---- Pred scan: decode + 9-row gather once per thread ----
    u64 lacc = 0ULL;
    if (tid < F4PB) {
        const float qa[4] = {q.x, q.y, q.z, q.w};
        const bool anyp = (qa[0] > 2.0f) | (qa[1] > 2.0f) |
                          (qa[2] > 2.0f) | (qa[3] > 2.0f);
        if (anyp) {
            const int loc = slice * VPB + tid * 4;   // all 4 voxels: same row
            const int z   = loc / 1600;
            const int rem = loc - z * 1600;
            const int y   = rem / 40;
            const int x0  = rem - y * 40;

            const u64* base = srow + (z - zlo + 1) * 42 + (y + 1);
            const u64 c0 = base[0];
            const u64 r1 = base[-1]  | base[1]  | base[-42] | base[42];
            const u64 r2 = base[-43] | base[-41] | base[41] | base[43];

#pragma unroll
            for (int c = 0; c < 4; ++c) {
                if (qa[c] > 2.0f) {
                    const int x = x0 + c;
                    int best = min(min(row_d2(c0, x),
                                       row_d2(r1, x) + 1),
                                       row_d2(r2, x) + 2);
                    // Rare fallback: expanding rings of whole rows (global).
                    // After ring r every unscanned row has dz^2+dy^2>=(r+1)^2.
                    if (best > 4) {
                        for (int r = 2; r <= 39; ++r) {
                            if (best <= r * r) break;
                            for (int dz = -r; dz <= r; ++dz) {
                                const int zz = z + dz;
                                if ((unsigned)zz >= 40u) continue;
                                const int step = (abs(dz) == r) ? 1 : 2 * r;
                                for (int dy = -r; dy <= r; dy += step) {
                                    const int yy = y + dy;
                                    if ((unsigned)yy >= 40u) continue;
                                    best = min(best, dz * dz + dy * dy +
                                                     global_row_d2(t, zz, yy, x));
                                }
                            }
                        }
                    }
                    // count in [56:40]; sum*2^20 in [39:0].
                    u64 add = 1ULL << 40;
                    if (best <= 4563)   // else: no true voxels -> distance 0
                        add += (u64)__float2uint_rn(sqrtf((float)best) *
                                                    1048576.0f);
                    lacc += add;
                }
            }
        }
    }

    // ---- Deterministic integer reduction (u64 adds) ----
#pragma unroll
    for (int off = 16; off; off >>= 1)
        lacc += __shfl_down_sync(0xffffffffu, lacc, off);
    if (lane == 0) wacc[warp] = lacc;
    __syncthreads();

    if (warp == 0) {
        u64 v = (lane < 16) ? wacc[lane] : 0ULL;
#pragma unroll
        for (int off = 8; off; off >>= 1)
            v += __shfl_down_sync(0xffffffffu, v, off);
        if (lane == 0) {
            const u64 contrib = v + (1ULL << 57);      // arrival marker
            const u64 old = atomicAdd(&g_acc, contrib);
            if ((old >> 57) == GRID - 1) {             // I'm the last arrival
                const u64 tot = old + contrib;
                const int cnt = (int)((tot >> 40) & 0x1FFFFULL);
                const double sum = (double)(tot & ((1ULL << 40) - 1ULL)) *
                                   (1.0 / 1048576.0);
                const float val = (cnt > 0) ? (float)(sum / (double)cnt) : 0.0f;
                for (int i = 0; i < out_size; ++i) out[i] = val;
                g_acc = 0ULL;   // reset for next graph replay
            }
        }
    }
}

extern "C" void kernel_launch(void* const* d_in, const int* in_sizes, int n_in,
                              void* d_out, int out_size) {
    const float* inp = (const float*)d_in[0];
    const float* tgt = (const float*)d_in[1];
    (void)in_sizes; (void)n_in;
    mdist_v6<<<GRID, TPB>>>(inp, tgt, (float*)d_out, out_size);
}

// round 7
// speedup vs baseline: 2.6937x; 1.0060x over previous
#include <cuda_runtime.h>
#include <math.h>

// Input: (2, 40, 40, 40) fp32. One block per (batch, z-plane).
#define NVOX   64000
#define GRID   80          // 2 batches * 40 planes
#define TPB    512
#define F4PB   400         // 1600 voxels per plane / 4
#define SROWN  210         // padded mask: (<=3+2 planes) * 42 y-slots

typedef unsigned long long u64;

// [63:57] arrivals, [56:40] pred count, [39:0] sum * 2^20.
// One integer atomicAdd per block: order-independent, bit-deterministic.
__device__ u64 g_acc = 0ULL;   // reset by last block (graph-replay safe)

// min over set bits of (bitpos - x)^2 ; ~(1<<20) sentinel if empty
__device__ __forceinline__ int row_d2(u64 w, int x) {
    u64 low  = w & ((2ULL << x) - 1ULL);   // bits 0..x
    u64 high = (w >> x) >> 1;              // bits x+1..
    int dl = low  ? (x - (63 - __clzll((long long)low))) : (1 << 10);
    int dh = high ? __ffsll((long long)high)             : (1 << 10);
    int d  = min(dl, dh);
    return d * d;
}

// Fallback only (P ~ 2^-33 per pred): scan a target row straight from global.
__device__ __noinline__ int global_row_d2(const float* __restrict__ t,
                                          int zz, int yy, int x) {
    const float* r = t + zz * 1600 + yy * 40;
    int best = 1 << 20;
    for (int xx = 0; xx < 40; ++xx)
        if (r[xx] > 0.0f) { int dx = xx - x; best = min(best, dx * dx); }
    return best;
}

__global__ __launch_bounds__(TPB, 1)
void mdist_v7(const float* __restrict__ inp, const float* __restrict__ tgt,
              float* __restrict__ out, int out_size) {
    __shared__ u64 srow[SROWN];
    __shared__ u64 wacc[16];

    const int tid   = threadIdx.x;
    const int bid   = blockIdx.x;
    const int lane  = tid & 31;
    const int warp  = tid >> 5;
    const int batch = bid >= 40;       // 40 planes per batch
    const int z     = bid - batch * 40;

    const float* t = tgt + batch * NVOX;

    // ---- Prefetch this thread's float4 of input (1600 voxels = 400 f4) ----
    float4 q = make_float4(0.f, 0.f, 0.f, 0.f);
    if (tid < F4PB)
        q = ((const float4*)inp)[batch * (NVOX / 4) + z * F4PB + tid];

    // ---- Zero padded mask early (covered by the sync below) ----
    if (tid < SROWN) srow[tid] = 0ULL;

    // ---- Plane z with +-1 halo: <= 3 planes, <= 120 rows ----
    const int zlo   = max(z - 1, 0);
    const int zhi   = min(z + 1, 39);
    const int nrows = (zhi - zlo + 1) * 40;

    // ---- Issue ALL target row loads up-front (one latency epoch) ----
    // Warp w handles rows r = w, w+16, ... (<= 8 slots -> <= 16 LDG).
    float va[8], vb[8];
#pragma unroll
    for (int i = 0; i < 8; ++i) {
        const int r = warp + i * 16;
        if (r < nrows) {
            const int off = (zlo * 40 + r) * 40;
            va[i] = t[off + lane];
            vb[i] = (lane < 8) ? t[off + 32 + lane] : -1.0f;
        }
    }
    __syncthreads();   // srow zeroing complete

    // ---- Ballot rows into padded shared mask ----
#pragma unroll
    for (int i = 0; i < 8; ++i) {
        const int r = warp + i * 16;
        if (r < nrows) {   // warp-uniform
            unsigned m0 = __ballot_sync(0xffffffffu, va[i] > 0.0f);
            unsigned m1 = __ballot_sync(0xffffffffu, vb[i] > 0.0f) & 0xffu;
            if (lane == 0) {
                const int pl = r / 40, yy = r - pl * 40;
                srow[(pl + 1) * 42 + yy + 1] = (u64)m0 | ((u64)m1 << 32);
            }
        }
    }
    __syncthreads();

    // ---- Pred scan: z constant per block; y = tid/10, x0 = (tid%10)*4 ----
    u64 lacc = 0ULL;
    if (tid < F4PB) {
        const float qa[4] = {q.x, q.y, q.z, q.w};
        const bool anyp = (qa[0] > 2.0f) | (qa[1] > 2.0f) |
                          (qa[2] > 2.0f) | (qa[3] > 2.0f);
        if (anyp) {
            const int y  = tid / 10;
            const int x0 = (tid - y * 10) * 4;

            const u64* base = srow + (z - zlo + 1) * 42 + (y + 1);
            const u64 c0 = base[0];
            const u64 r1 = base[-1]  | base[1]  | base[-42] | base[42];
            const u64 r2 = base[-43] | base[-41] | base[41] | base[43];

#pragma unroll
            for (int c = 0; c < 4; ++c) {
                if (qa[c] > 2.0f) {
                    const int x = x0 + c;
                    int best = min(min(row_d2(c0, x),
                                       row_d2(r1, x) + 1),
                                       row_d2(r2, x) + 2);
                    // Rare fallback: expanding rings of whole rows (global).
                    // After ring r every unscanned row has dz^2+dy^2>=(r+1)^2.
                    if (best > 4) {
                        for (int r = 2; r <= 39; ++r) {
                            if (best <= r * r) break;
                            for (int dz = -r; dz <= r; ++dz) {
                                const int zz = z + dz;
                                if ((unsigned)zz >= 40u) continue;
                                const int step = (abs(dz) == r) ? 1 : 2 * r;
                                for (int dy = -r; dy <= r; dy += step) {
                                    const int yy = y + dy;
                                    if ((unsigned)yy >= 40u) continue;
                                    best = min(best, dz * dz + dy * dy +
                                                     global_row_d2(t, zz, yy, x));
                                }
                            }
                        }
                    }
                    // count in [56:40]; sum*2^20 in [39:0].
                    u64 add = 1ULL << 40;
                    if (best <= 4563)   // else: no true voxels -> distance 0
                        add += (u64)__float2uint_rn(sqrtf((float)best) *
                                                    1048576.0f);
                    lacc += add;
                }
            }
        }
    }

    // ---- Deterministic integer reduction (u64 adds) ----
#pragma unroll
    for (int off = 16; off; off >>= 1)
        lacc += __shfl_down_sync(0xffffffffu, lacc, off);
    if (lane == 0) wacc[warp] = lacc;
    __syncthreads();

    if (warp == 0) {
        u64 v = (lane < 16) ? wacc[lane] : 0ULL;
#pragma unroll
        for (int off = 8; off; off >>= 1)
            v += __shfl_down_sync(0xffffffffu, v, off);
        if (lane == 0) {
            const u64 contrib = v + (1ULL << 57);      // arrival marker
            const u64 old = atomicAdd(&g_acc, contrib);
            if ((old >> 57) == GRID - 1) {             // I'm the last arrival
                const u64 tot = old + contrib;
                const int cnt = (int)((tot >> 40) & 0x1FFFFULL);
                const double sum = (double)(tot & ((1ULL << 40) - 1ULL)) *
                                   (1.0 / 1048576.0);
                const float val = (cnt > 0) ? (float)(sum / (double)cnt) : 0.0f;
                for (int i = 0; i < out_size; ++i) out[i] = val;
                g_acc = 0ULL;   // reset for next graph replay
            }
        }
    }
}

extern "C" void kernel_launch(void* const* d_in, const int* in_sizes, int n_in,
                              void* d_out, int out_size) {
    const float* inp = (const float*)d_in[0];
    const float* tgt = (const float*)d_in[1];
    (void)in_sizes; (void)n_in;
    mdist_v7<<<GRID, TPB>>>(inp, tgt, (float*)d_out, out_size);
}

// round 8
// speedup vs baseline: 3.2151x; 1.1935x over previous
#include <cuda_runtime.h>
#include <math.h>

// Input: (2, 40, 40, 40) fp32. One block per (batch, z-plane).
#define NVOX   64000
#define GRID   80          // 2 batches * 40 planes
#define TPB    512
#define F4PB   400         // 1600 voxels per plane / 4
#define SROWN  210         // padded row mask: 5 plane-slots * 42 y-slots
#define NBROWS 120         // max rows in 3-plane window
#define SBYTEW 16          // padded bytes per staging row

typedef unsigned long long u64;

// [63:57] arrivals, [56:40] pred count, [39:0] sum * 2^20.
// One integer atomicAdd per block: order-independent, bit-deterministic.
__device__ u64 g_acc = 0ULL;   // reset by last block (graph-replay safe)

// min over set bits of (bitpos - x)^2 ; ~(1<<20) sentinel if empty
__device__ __forceinline__ int row_d2(u64 w, int x) {
    u64 low  = w & ((2ULL << x) - 1ULL);   // bits 0..x
    u64 high = (w >> x) >> 1;              // bits x+1..
    int dl = low  ? (x - (63 - __clzll((long long)low))) : (1 << 10);
    int dh = high ? __ffsll((long long)high)             : (1 << 10);
    int d  = min(dl, dh);
    return d * d;
}

// Pack 8 nibble-valued bytes (u64) into 32 bits.
__device__ __forceinline__ unsigned pack8(u64 B) {
    u64 x = (B | (B >> 4))  & 0x00FF00FF00FF00FFULL;
    x     = (x | (x >> 8))  & 0x0000FFFF0000FFFFULL;
    x     = (x | (x >> 16));
    return (unsigned)x;
}

// Fallback only (P ~ 2^-33 per pred): scan a target row straight from global.
__device__ __noinline__ int global_row_d2(const float* __restrict__ t,
                                          int zz, int yy, int x) {
    const float* r = t + zz * 1600 + yy * 40;
    int best = 1 << 20;
    for (int xx = 0; xx < 40; ++xx)
        if (r[xx] > 0.0f) { int dx = xx - x; best = min(best, dx * dx); }
    return best;
}

__global__ __launch_bounds__(TPB, 1)
void mdist_v8(const float* __restrict__ inp, const float* __restrict__ tgt,
              float* __restrict__ out, int out_size) {
    __shared__ u64           srow[SROWN];
    __shared__ unsigned char sbyte[NBROWS * SBYTEW];   // nibble staging
    __shared__ u64           wacc[16];

    const int tid   = threadIdx.x;
    const int bid   = blockIdx.x;
    const int lane  = tid & 31;
    const int warp  = tid >> 5;
    const int batch = bid >= 40;       // 40 planes per batch
    const int z     = bid - batch * 40;

    const float* t = tgt + batch * NVOX;

    // ---- Zero staging + padded mask (450 u64 slots over 512 threads) ----
    if (tid < SROWN) srow[tid] = 0ULL;
    if (tid < NBROWS * SBYTEW / 8) ((u64*)sbyte)[tid] = 0ULL;

    // ---- Prefetch this thread's float4 of input (400 f4 per plane) ----
    float4 q = make_float4(0.f, 0.f, 0.f, 0.f);
    if (tid < F4PB)
        q = ((const float4*)inp)[batch * (NVOX / 4) + z * F4PB + tid];

    // ---- Window: plane z with +-1 halo (<= 3 planes) ----
    const int zlo  = max(z - 1, 0);
    const int zhi  = min(z + 1, 39);
    const int nf4  = (zhi - zlo + 1) * F4PB;       // <= 1200
    const int nrow = (zhi - zlo + 1) * 40;         // <= 120

    // ---- Target: float4 loads -> nibble per thread-slot ----
    const float4* tw = (const float4*)(t + zlo * 1600);
    float4 tv[3]; int js[3];
#pragma unroll
    for (int s = 0; s < 3; ++s) {
        const int j = tid + s * TPB;
        js[s] = j;
        if (j < nf4) tv[s] = tw[j];
    }
    __syncthreads();   // zeroing complete
#pragma unroll
    for (int s = 0; s < 3; ++s) {
        const int j = js[s];
        if (j < nf4) {
            const unsigned bits = (tv[s].x > 0.0f)       |
                                  ((tv[s].y > 0.0f) << 1) |
                                  ((tv[s].z > 0.0f) << 2) |
                                  ((tv[s].w > 0.0f) << 3);
            const int row = j / 10;
            sbyte[row * SBYTEW + (j - row * 10)] = (unsigned char)bits;
        }
    }
    __syncthreads();

    // ---- Assemble row words (one thread per row, no ballots) ----
    if (tid < nrow) {
        const u64 lo = *(const u64*)(sbyte + tid * SBYTEW);
        const unsigned hi2 = *(const unsigned short*)(sbyte + tid * SBYTEW + 8);
        const unsigned hi = (hi2 & 0xFu) | ((hi2 >> 4) & 0xF0u);  // n8|n9<<4
        const u64 w = (u64)pack8(lo) | ((u64)hi << 32);
        const int pl = tid / 40, yy = tid - pl * 40;
        srow[(pl + 1) * 42 + yy + 1] = w;
    }
    __syncthreads();

    // ---- Pred scan: z constant per block; y = tid/10, x0 = (tid%10)*4 ----
    u64 lacc = 0ULL;
    if (tid < F4PB) {
        const float qa[4] = {q.x, q.y, q.z, q.w};
        const bool anyp = (qa[0] > 2.0f) | (qa[1] > 2.0f) |
                          (qa[2] > 2.0f) | (qa[3] > 2.0f);
        if (anyp) {
            const int y  = tid / 10;
            const int x0 = (tid - y * 10) * 4;

            const u64* base = srow + (z - zlo + 1) * 42 + (y + 1);
            const u64 c0 = base[0];
            const u64 r1 = base[-1]  | base[1]  | base[-42] | base[42];
            const u64 r2 = base[-43] | base[-41] | base[41] | base[43];

#pragma unroll
            for (int c = 0; c < 4; ++c) {
                if (qa[c] > 2.0f) {
                    const int x = x0 + c;
                    int best = min(min(row_d2(c0, x),
                                       row_d2(r1, x) + 1),
                                       row_d2(r2, x) + 2);
                    // Rare fallback: expanding rings of whole rows (global).
                    // After ring r every unscanned row has dz^2+dy^2>=(r+1)^2.
                    if (best > 4) {
                        for (int r = 2; r <= 39; ++r) {
                            if (best <= r * r) break;
                            for (int dz = -r; dz <= r; ++dz) {
                                const int zz = z + dz;
                                if ((unsigned)zz >= 40u) continue;
                                const int step = (abs(dz) == r) ? 1 : 2 * r;
                                for (int dy = -r; dy <= r; dy += step) {
                                    const int yy = y + dy;
                                    if ((unsigned)yy >= 40u) continue;
                                    best = min(best, dz * dz + dy * dy +
                                                     global_row_d2(t, zz, yy, x));
                                }
                            }
                        }
                    }
                    // count in [56:40]; sum*2^20 in [39:0].
                    u64 add = 1ULL << 40;
                    if (best <= 4563)   // else: no true voxels -> distance 0
                        add += (u64)__float2uint_rn(sqrtf((float)best) *
                                                    1048576.0f);
                    lacc += add;
                }
            }
        }
    }

    // ---- Deterministic integer reduction (u64 adds) ----
#pragma unroll
    for (int off = 16; off; off >>= 1)
        lacc += __shfl_down_sync(0xffffffffu, lacc, off);
    if (lane == 0) wacc[warp] = lacc;
    __syncthreads();

    if (warp == 0) {
        u64 v = (lane < 16) ? wacc[lane] : 0ULL;
#pragma unroll
        for (int off = 8; off; off >>= 1)
            v += __shfl_down_sync(0xffffffffu, v, off);
        if (lane == 0) {
            const u64 contrib = v + (1ULL << 57);      // arrival marker
            const u64 old = atomicAdd(&g_acc, contrib);
            if ((old >> 57) == GRID - 1) {             // I'm the last arrival
                const u64 tot = old + contrib;
                const int cnt = (int)((tot >> 40) & 0x1FFFFULL);
                const double sum = (double)(tot & ((1ULL << 40) - 1ULL)) *
                                   (1.0 / 1048576.0);
                const float val = (cnt > 0) ? (float)(sum / (double)cnt) : 0.0f;
                for (int i = 0; i < out_size; ++i) out[i] = val;
                g_acc = 0ULL;   // reset for next graph replay
            }
        }
    }
}

extern "C" void kernel_launch(void* const* d_in, const int* in_sizes, int n_in,
                              void* d_out, int out_size) {
    const float* inp = (const float*)d_in[0];
    const float* tgt = (const float*)d_in[1];
    (void)in_sizes; (void)n_in;
    mdist_v8<<<GRID, TPB>>>(inp, tgt, (float*)d_out, out_size);
}